// round 5
// baseline (speedup 1.0000x reference)
#include <cuda_runtime.h>

#define N_NODES 50000
#define N_EDGES 600000
#define N_LABEL 200000
#define CH      128

#define SCAN_BLOCKS 196   // 196*256 = 50176 >= N_NODES
#define SCAN_TPB    256

// ---------------- device scratch (static; no runtime allocation) ------------
__device__ int   g_indeg [N_NODES];
__device__ int   g_cursor[N_NODES];
__device__ int   g_offs  [N_NODES + 1];
__device__ float g_dinv  [N_NODES];
__device__ int   g_bsums [SCAN_BLOCKS];
__device__ int2  g_csr   [N_EDGES];          // .x = src, .y = float bits of w
__device__ float g_hA  [N_NODES * CH];
__device__ float g_hB  [N_NODES * CH];
__device__ float g_z   [N_NODES * CH];

// ---------------- f32x2 packed helpers (Blackwell) --------------------------
__device__ __forceinline__ unsigned long long pack2(float lo, float hi) {
    unsigned long long r;
    asm("mov.b64 %0, {%1, %2};" : "=l"(r) : "f"(lo), "f"(hi));
    return r;
}
__device__ __forceinline__ unsigned long long bcast2(float v) {
    unsigned long long r;
    asm("mov.b64 %0, {%1, %1};" : "=l"(r) : "f"(v));
    return r;
}
__device__ __forceinline__ void fma2(unsigned long long& d,
                                     unsigned long long a,
                                     unsigned long long b) {
    asm("fma.rn.f32x2 %0, %1, %2, %0;" : "+l"(d) : "l"(a), "l"(b));
}
__device__ __forceinline__ void unpack2(float& lo, float& hi,
                                        unsigned long long v) {
    asm("mov.b64 {%0, %1}, %2;" : "=f"(lo), "=f"(hi) : "l"(v));
}

// ---------------- CSR build --------------------------------------------------
__global__ void csr_init_kernel() {
    int i = blockIdx.x * blockDim.x + threadIdx.x;
    if (i < N_NODES) { g_indeg[i] = 0; g_cursor[i] = 0; }
}

__global__ void indeg_kernel(const int* __restrict__ ei) {
    int e = blockIdx.x * blockDim.x + threadIdx.x;
    if (e < N_EDGES) atomicAdd(&g_indeg[ei[N_EDGES + e]], 1);
}

// phase A: per-block sum of indeg; also compute dinv
__global__ void scanA_kernel() {
    __shared__ int wsum[8];
    int i = blockIdx.x * SCAN_TPB + threadIdx.x;
    int lane = threadIdx.x & 31, wid = threadIdx.x >> 5;
    int v = (i < N_NODES) ? g_indeg[i] : 0;
    if (i < N_NODES) g_dinv[i] = rsqrtf((float)(v + 1));
    int s = v;
#pragma unroll
    for (int off = 16; off > 0; off >>= 1)
        s += __shfl_down_sync(0xffffffffu, s, off);
    if (lane == 0) wsum[wid] = s;
    __syncthreads();
    if (wid == 0) {
        int t = (lane < 8) ? wsum[lane] : 0;
#pragma unroll
        for (int off = 4; off > 0; off >>= 1)
            t += __shfl_down_sync(0xffffffffu, t, off);
        if (lane == 0) g_bsums[blockIdx.x] = t;
    }
}

// phase B: single block, exclusive scan of the 196 block sums
__global__ void scanB_kernel() {
    __shared__ int wsum[8];
    int tid = threadIdx.x, lane = tid & 31, wid = tid >> 5;
    int v = (tid < SCAN_BLOCKS) ? g_bsums[tid] : 0;
    int inc = v;
#pragma unroll
    for (int off = 1; off < 32; off <<= 1) {
        int t = __shfl_up_sync(0xffffffffu, inc, off);
        if (lane >= off) inc += t;
    }
    if (lane == 31) wsum[wid] = inc;
    __syncthreads();
    if (wid == 0) {
        int w = (lane < 8) ? wsum[lane] : 0;
#pragma unroll
        for (int off = 1; off < 8; off <<= 1) {
            int t = __shfl_up_sync(0xffffffffu, w, off);
            if (lane >= off) w += t;
        }
        if (lane < 8) wsum[lane] = w;
    }
    __syncthreads();
    int excl = inc - v + ((wid > 0) ? wsum[wid - 1] : 0);
    if (tid < SCAN_BLOCKS) g_bsums[tid] = excl;
}

// phase C: block-local scan + block base -> g_offs
__global__ void scanC_kernel() {
    __shared__ int wsum[8];
    int i = blockIdx.x * SCAN_TPB + threadIdx.x;
    int lane = threadIdx.x & 31, wid = threadIdx.x >> 5;
    int v = (i < N_NODES) ? g_indeg[i] : 0;
    int inc = v;
#pragma unroll
    for (int off = 1; off < 32; off <<= 1) {
        int t = __shfl_up_sync(0xffffffffu, inc, off);
        if (lane >= off) inc += t;
    }
    if (lane == 31) wsum[wid] = inc;
    __syncthreads();
    if (wid == 0) {
        int w = (lane < 8) ? wsum[lane] : 0;
#pragma unroll
        for (int off = 1; off < 8; off <<= 1) {
            int t = __shfl_up_sync(0xffffffffu, w, off);
            if (lane >= off) w += t;
        }
        if (lane < 8) wsum[lane] = w;
    }
    __syncthreads();
    int excl = inc - v + ((wid > 0) ? wsum[wid - 1] : 0) + g_bsums[blockIdx.x];
    if (i < N_NODES) g_offs[i] = excl;
    if (i == N_NODES - 1) g_offs[N_NODES] = excl + v;
}

__global__ void csr_fill_kernel(const int* __restrict__ ei) {
    int e = blockIdx.x * blockDim.x + threadIdx.x;
    if (e >= N_EDGES) return;
    int s = ei[e];
    int d = ei[N_EDGES + e];
    int p = g_offs[d] + atomicAdd(&g_cursor[d], 1);
    float w = g_dinv[s] * g_dinv[d];
    g_csr[p] = make_int2(s, __float_as_int(w));
}

// ---------------- propagation: CSR gather, 8-deep pipeline ------------------
__global__ void __launch_bounds__(256) gather_kernel(
        const float* __restrict__ hin, float* __restrict__ hout) {
    int t = blockIdx.x * blockDim.x + threadIdx.x;
    int i = t >> 5, lane = t & 31;
    if (i >= N_NODES) return;
    float di = g_dinv[i];
    float w0 = di * di;
    float4 v = ((const float4*)(hin + (size_t)i * CH))[lane];
    float4 acc = make_float4(v.x * w0, v.y * w0, v.z * w0, v.w * w0);

    int k   = g_offs[i];
    int end = g_offs[i + 1];
    int n   = end - k;

    while (n >= 8) {
        int2 e[8];
#pragma unroll
        for (int q = 0; q < 8; q++) e[q] = g_csr[k + q];
        float4 u[8];
#pragma unroll
        for (int q = 0; q < 8; q++)
            u[q] = ((const float4*)(hin + (size_t)e[q].x * CH))[lane];
#pragma unroll
        for (int q = 0; q < 8; q++) {
            float w = __int_as_float(e[q].y);
            acc.x += w * u[q].x; acc.y += w * u[q].y;
            acc.z += w * u[q].z; acc.w += w * u[q].w;
        }
        k += 8; n -= 8;
    }
    if (n >= 4) {
        int2 e[4];
#pragma unroll
        for (int q = 0; q < 4; q++) e[q] = g_csr[k + q];
        float4 u[4];
#pragma unroll
        for (int q = 0; q < 4; q++)
            u[q] = ((const float4*)(hin + (size_t)e[q].x * CH))[lane];
#pragma unroll
        for (int q = 0; q < 4; q++) {
            float w = __int_as_float(e[q].y);
            acc.x += w * u[q].x; acc.y += w * u[q].y;
            acc.z += w * u[q].z; acc.w += w * u[q].w;
        }
        k += 4; n -= 4;
    }
    if (n >= 2) {
        int2 e0 = g_csr[k], e1 = g_csr[k + 1];
        float4 u0 = ((const float4*)(hin + (size_t)e0.x * CH))[lane];
        float4 u1 = ((const float4*)(hin + (size_t)e1.x * CH))[lane];
        float wa = __int_as_float(e0.y), wb = __int_as_float(e1.y);
        acc.x += wa * u0.x; acc.y += wa * u0.y; acc.z += wa * u0.z; acc.w += wa * u0.w;
        acc.x += wb * u1.x; acc.y += wb * u1.y; acc.z += wb * u1.z; acc.w += wb * u1.w;
        k += 2; n -= 2;
    }
    if (n >= 1) {
        int2 e = g_csr[k];
        float w = __int_as_float(e.y);
        float4 u = ((const float4*)(hin + (size_t)e.x * CH))[lane];
        acc.x += w * u.x; acc.y += w * u.y; acc.z += w * u.z; acc.w += w * u.w;
    }
    ((float4*)(hout + (size_t)i * CH))[lane] = acc;
}

// ---------------- z = h @ W^T + bias  (tiled GEMM, f32x2 packed) ------------
__global__ void zgemm_kernel(const float* __restrict__ A,
                             const float* __restrict__ W,
                             const float* __restrict__ bias,
                             float* __restrict__ C) {
    __shared__ float As[32][64 + 4];    // [k][m]
    __shared__ float Bs[32][128 + 4];   // [k][n]
    int tid = threadIdx.x;
    int m0  = blockIdx.x * 64;
    int tm  = tid >> 4;
    int tn  = tid & 15;

    unsigned long long acc2[4][4];      // [row][n-pair]
#pragma unroll
    for (int i = 0; i < 4; i++)
#pragma unroll
        for (int j = 0; j < 4; j++) acc2[i][j] = 0ull;

    for (int kb = 0; kb < 4; kb++) {
        int k0 = kb * 32;
#pragma unroll
        for (int it = 0; it < 8; it++) {
            int idx = it * 256 + tid;
            int m = idx >> 5, k = idx & 31;
            int row = m0 + m;
            As[k][m] = (row < N_NODES) ? A[(size_t)row * CH + k0 + k] : 0.0f;
        }
#pragma unroll
        for (int it = 0; it < 16; it++) {
            int idx = it * 256 + tid;
            int n = idx >> 5, k = idx & 31;
            Bs[k][n] = W[(size_t)n * CH + k0 + k];
        }
        __syncthreads();
#pragma unroll
        for (int k = 0; k < 32; k++) {
            float4 av  = *(const float4*)&As[k][tm * 4];
            float4 bv0 = *(const float4*)&Bs[k][tn * 8];
            float4 bv1 = *(const float4*)&Bs[k][tn * 8 + 4];
            unsigned long long b[4];
            b[0] = pack2(bv0.x, bv0.y);
            b[1] = pack2(bv0.z, bv0.w);
            b[2] = pack2(bv1.x, bv1.y);
            b[3] = pack2(bv1.z, bv1.w);
            unsigned long long a0 = bcast2(av.x), a1 = bcast2(av.y);
            unsigned long long a2 = bcast2(av.z), a3 = bcast2(av.w);
#pragma unroll
            for (int j = 0; j < 4; j++) {
                fma2(acc2[0][j], a0, b[j]);
                fma2(acc2[1][j], a1, b[j]);
                fma2(acc2[2][j], a2, b[j]);
                fma2(acc2[3][j], a3, b[j]);
            }
        }
        __syncthreads();
    }
#pragma unroll
    for (int i = 0; i < 4; i++) {
        int row = m0 + tm * 4 + i;
        if (row >= N_NODES) break;
#pragma unroll
        for (int j = 0; j < 4; j++) {
            float lo, hi;
            unpack2(lo, hi, acc2[i][j]);
            int col = tn * 8 + j * 2;
            C[(size_t)row * CH + col]     = lo + bias[col];
            C[(size_t)row * CH + col + 1] = hi + bias[col + 1];
        }
    }
}

// ---------------- decode: r = w2 . relu(W1 (z[a]*z[b]) + b1) + b2 -----------
__global__ void decode_kernel(const float* __restrict__ z,
                              const int* __restrict__ eli,
                              const float* __restrict__ w1,
                              const float* __restrict__ b1,
                              const float* __restrict__ w2,
                              const float* __restrict__ b2,
                              float* __restrict__ out) {
    extern __shared__ float sm[];
    float* s_sm  = sm;               // [128][64]
    float* w1_sm = sm + 128 * 64;    // [128][64]
    __shared__ float acc_sm[64];

    int tid = threadIdx.x;
    int e0  = blockIdx.x * 64;

#pragma unroll
    for (int it = 0; it < 32; it++) {
        int idx = it * 256 + tid;
        int j = idx >> 7, c = idx & 127;
        w1_sm[c * 64 + j] = w1[idx];
    }

    {
        int ee = tid >> 2, q = tid & 3;
        int e  = e0 + ee;
        int a  = eli[e];
        int b  = eli[N_LABEL + e];
        const float4* za4 = (const float4*)(z + (size_t)a * CH);
        const float4* zb4 = (const float4*)(z + (size_t)b * CH);
#pragma unroll
        for (int r = 0; r < 8; r++) {
            int c4 = r * 4 + q;
            float4 x1 = za4[c4];
            float4 x2 = zb4[c4];
            int c = c4 * 4;
            s_sm[(c + 0) * 64 + ee] = x1.x * x2.x;
            s_sm[(c + 1) * 64 + ee] = x1.y * x2.y;
            s_sm[(c + 2) * 64 + ee] = x1.z * x2.z;
            s_sm[(c + 3) * 64 + ee] = x1.w * x2.w;
        }
    }
    if (tid < 64) acc_sm[tid] = b2[0];
    __syncthreads();

    int te = tid & 15;   // edge group
    int tj = tid >> 4;   // j group
    unsigned long long acc2[4][2];   // [edge][j-pair]
#pragma unroll
    for (int i = 0; i < 4; i++) { acc2[i][0] = 0ull; acc2[i][1] = 0ull; }

#pragma unroll 4
    for (int c = 0; c < 128; c++) {
        float4 sv = *(const float4*)&s_sm [c * 64 + te * 4];
        float4 wv = *(const float4*)&w1_sm[c * 64 + tj * 4];
        unsigned long long b0 = pack2(wv.x, wv.y);
        unsigned long long b1p = pack2(wv.z, wv.w);
        unsigned long long a0 = bcast2(sv.x), a1 = bcast2(sv.y);
        unsigned long long a2 = bcast2(sv.z), a3 = bcast2(sv.w);
        fma2(acc2[0][0], a0, b0);  fma2(acc2[0][1], a0, b1p);
        fma2(acc2[1][0], a1, b0);  fma2(acc2[1][1], a1, b1p);
        fma2(acc2[2][0], a2, b0);  fma2(acc2[2][1], a2, b1p);
        fma2(acc2[3][0], a3, b0);  fma2(acc2[3][1], a3, b1p);
    }

    float p[4] = {0.0f, 0.0f, 0.0f, 0.0f};
#pragma unroll
    for (int jp = 0; jp < 2; jp++) {
        int j0 = tj * 4 + jp * 2;
        float bb0 = b1[j0],     ww0 = w2[j0];
        float bb1 = b1[j0 + 1], ww1 = w2[j0 + 1];
#pragma unroll
        for (int ie = 0; ie < 4; ie++) {
            float lo, hi;
            unpack2(lo, hi, acc2[ie][jp]);
            float h0 = lo + bb0;
            float h1 = hi + bb1;
            if (h0 > 0.0f) p[ie] += h0 * ww0;
            if (h1 > 0.0f) p[ie] += h1 * ww1;
        }
    }
#pragma unroll
    for (int ie = 0; ie < 4; ie++)
        atomicAdd(&acc_sm[te * 4 + ie], p[ie]);
    __syncthreads();

    if (tid < 64) out[e0 + tid] = acc_sm[tid];
}

// ---------------- launch ------------------------------------------------------
extern "C" void kernel_launch(void* const* d_in, const int* in_sizes, int n_in,
                              void* d_out, int out_size) {
    const float* x    = (const float*)d_in[0];
    const int*   ei   = (const int*)  d_in[1];
    const int*   eli  = (const int*)  d_in[2];
    const float* cw   = (const float*)d_in[3];
    const float* cb   = (const float*)d_in[4];
    const float* w1   = (const float*)d_in[5];
    const float* b1   = (const float*)d_in[6];
    const float* w2   = (const float*)d_in[7];
    const float* b2   = (const float*)d_in[8];
    float*       out  = (float*)d_out;

    float *hA, *hB, *zz;
    cudaGetSymbolAddress((void**)&hA, g_hA);
    cudaGetSymbolAddress((void**)&hB, g_hB);
    cudaGetSymbolAddress((void**)&zz, g_z);

    // CSR build
    csr_init_kernel<<<(N_NODES + 255) / 256, 256>>>();
    indeg_kernel   <<<(N_EDGES + 255) / 256, 256>>>(ei);
    scanA_kernel   <<<SCAN_BLOCKS, SCAN_TPB>>>();
    scanB_kernel   <<<1, 256>>>();
    scanC_kernel   <<<SCAN_BLOCKS, SCAN_TPB>>>();
    csr_fill_kernel<<<(N_EDGES + 255) / 256, 256>>>(ei);

    // 2-hop propagation via gather
    gather_kernel<<<(N_NODES * 32 + 255) / 256, 256>>>(x,  hA);
    gather_kernel<<<(N_NODES * 32 + 255) / 256, 256>>>(hA, hB);

    // z = hB @ W^T + b
    zgemm_kernel<<<(N_NODES + 63) / 64, 256>>>(hB, cw, cb, zz);

    // decode
    cudaFuncSetAttribute(decode_kernel,
                         cudaFuncAttributeMaxDynamicSharedMemorySize,
                         128 * 64 * 2 * sizeof(float));
    decode_kernel<<<N_LABEL / 64, 256, 128 * 64 * 2 * sizeof(float)>>>(
        zz, eli, w1, b1, w2, b2, out);
}

// round 6
// speedup vs baseline: 1.1974x; 1.1974x over previous
#include <cuda_runtime.h>

#define N_NODES 50000
#define N_EDGES 600000
#define N_LABEL 200000
#define CH      128

#define SCAN_BLOCKS 196   // 196*256 = 50176 >= N_NODES
#define SCAN_TPB    256

// ---------------- device scratch (zero-init at load; cleanup re-zeros) ------
__device__ int   g_indeg [N_NODES];          // must be 0 at pipeline start
__device__ int   g_cursor[N_NODES];          // must be 0 at pipeline start
__device__ int   g_scan_state[SCAN_BLOCKS];  // must be 0 at pipeline start
__device__ int   g_scan_agg  [SCAN_BLOCKS];
__device__ int   g_offs  [N_NODES + 1];
__device__ float g_dinv  [N_NODES];
__device__ int2  g_csr   [N_EDGES];          // .x = src, .y = float bits of w
__device__ float g_hA  [N_NODES * CH];
__device__ float g_hB  [N_NODES * CH];
__device__ float g_z   [N_NODES * CH];

// ---------------- f32x2 packed helpers (Blackwell) --------------------------
__device__ __forceinline__ void fma2(unsigned long long& d,
                                     unsigned long long a,
                                     unsigned long long b) {
    asm("fma.rn.f32x2 %0, %1, %2, %0;" : "+l"(d) : "l"(a), "l"(b));
}
__device__ __forceinline__ void unpack2(float& lo, float& hi,
                                        unsigned long long v) {
    asm("mov.b64 {%0, %1}, %2;" : "=f"(lo), "=f"(hi) : "l"(v));
}
__device__ __forceinline__ unsigned long long pack2(float lo, float hi) {
    unsigned long long r;
    asm("mov.b64 %0, {%1, %2};" : "=l"(r) : "f"(lo), "f"(hi));
    return r;
}
__device__ __forceinline__ unsigned long long bcast2(float v) {
    unsigned long long r;
    asm("mov.b64 %0, {%1, %1};" : "=l"(r) : "f"(v));
    return r;
}

// ---------------- launch 0: in-degree ---------------------------------------
__global__ void indeg_kernel(const int* __restrict__ ei) {
    int e = blockIdx.x * blockDim.x + threadIdx.x;
    if (e < N_EDGES) atomicAdd(&g_indeg[ei[N_EDGES + e]], 1);
}

// ---------------- launch 1: fused scan (lookback) + dinv --------------------
__global__ void __launch_bounds__(SCAN_TPB) scanF_kernel() {
    __shared__ int wsum[8];
    __shared__ int rsum[8];
    __shared__ int sbase;
    int tid  = threadIdx.x;
    int bid  = blockIdx.x;
    int lane = tid & 31, wid = tid >> 5;
    int i = bid * SCAN_TPB + tid;

    int v = (i < N_NODES) ? g_indeg[i] : 0;
    if (i < N_NODES) g_dinv[i] = rsqrtf((float)(v + 1));

    // block inclusive scan
    int inc = v;
#pragma unroll
    for (int off = 1; off < 32; off <<= 1) {
        int t = __shfl_up_sync(0xffffffffu, inc, off);
        if (lane >= off) inc += t;
    }
    if (lane == 31) wsum[wid] = inc;
    __syncthreads();
    if (wid == 0) {
        int w = (lane < 8) ? wsum[lane] : 0;
#pragma unroll
        for (int off = 1; off < 8; off <<= 1) {
            int t = __shfl_up_sync(0xffffffffu, w, off);
            if (lane >= off) w += t;
        }
        if (lane < 8) wsum[lane] = w;
    }
    __syncthreads();
    int binc  = inc + ((wid > 0) ? wsum[wid - 1] : 0); // inclusive within block
    int total = wsum[7];

    // publish aggregate (release)
    if (tid == 0) {
        g_scan_agg[bid] = total;
        asm volatile("st.release.gpu.b32 [%0], %1;"
                     :: "l"(&g_scan_state[bid]), "r"(1) : "memory");
    }

    // lookback: sum all preceding block aggregates
    int part = 0;
    for (int t = tid; t < bid; t += SCAN_TPB) {
        int st;
        do {
            asm volatile("ld.acquire.gpu.b32 %0, [%1];"
                         : "=r"(st) : "l"(&g_scan_state[t]));
        } while (st == 0);
        part += g_scan_agg[t];
    }
    // block reduce part
#pragma unroll
    for (int off = 16; off > 0; off >>= 1)
        part += __shfl_down_sync(0xffffffffu, part, off);
    if (lane == 0) rsum[wid] = part;
    __syncthreads();
    if (wid == 0) {
        int t = (lane < 8) ? rsum[lane] : 0;
#pragma unroll
        for (int off = 4; off > 0; off >>= 1)
            t += __shfl_down_sync(0xffffffffu, t, off);
        if (lane == 0) sbase = t;
    }
    __syncthreads();
    int excl = sbase + binc - v;
    if (i < N_NODES) g_offs[i] = excl;
    if (i == N_NODES - 1) g_offs[N_NODES] = excl + v;
}

// ---------------- launch 2: CSR fill ----------------------------------------
__global__ void csr_fill_kernel(const int* __restrict__ ei) {
    int e = blockIdx.x * blockDim.x + threadIdx.x;
    if (e >= N_EDGES) return;
    int s = ei[e];
    int d = ei[N_EDGES + e];
    int p = g_offs[d] + atomicAdd(&g_cursor[d], 1);
    float w = g_dinv[s] * g_dinv[d];
    g_csr[p] = make_int2(s, __float_as_int(w));
}

// ---------------- launches 3,4: CSR gather, 8-deep pipeline -----------------
__global__ void __launch_bounds__(256) gather_kernel(
        const float* __restrict__ hin, float* __restrict__ hout) {
    int t = blockIdx.x * blockDim.x + threadIdx.x;
    int i = t >> 5, lane = t & 31;
    if (i >= N_NODES) return;
    float di = g_dinv[i];
    float w0 = di * di;
    float4 v = ((const float4*)(hin + (size_t)i * CH))[lane];
    float4 acc = make_float4(v.x * w0, v.y * w0, v.z * w0, v.w * w0);

    int k   = g_offs[i];
    int end = g_offs[i + 1];
    int n   = end - k;

    while (n >= 8) {
        int2 e[8];
#pragma unroll
        for (int q = 0; q < 8; q++) e[q] = g_csr[k + q];
        float4 u[8];
#pragma unroll
        for (int q = 0; q < 8; q++)
            u[q] = ((const float4*)(hin + (size_t)e[q].x * CH))[lane];
#pragma unroll
        for (int q = 0; q < 8; q++) {
            float w = __int_as_float(e[q].y);
            acc.x += w * u[q].x; acc.y += w * u[q].y;
            acc.z += w * u[q].z; acc.w += w * u[q].w;
        }
        k += 8; n -= 8;
    }
    if (n >= 4) {
        int2 e[4];
#pragma unroll
        for (int q = 0; q < 4; q++) e[q] = g_csr[k + q];
        float4 u[4];
#pragma unroll
        for (int q = 0; q < 4; q++)
            u[q] = ((const float4*)(hin + (size_t)e[q].x * CH))[lane];
#pragma unroll
        for (int q = 0; q < 4; q++) {
            float w = __int_as_float(e[q].y);
            acc.x += w * u[q].x; acc.y += w * u[q].y;
            acc.z += w * u[q].z; acc.w += w * u[q].w;
        }
        k += 4; n -= 4;
    }
    if (n >= 2) {
        int2 e0 = g_csr[k], e1 = g_csr[k + 1];
        float4 u0 = ((const float4*)(hin + (size_t)e0.x * CH))[lane];
        float4 u1 = ((const float4*)(hin + (size_t)e1.x * CH))[lane];
        float wa = __int_as_float(e0.y), wb = __int_as_float(e1.y);
        acc.x += wa * u0.x; acc.y += wa * u0.y; acc.z += wa * u0.z; acc.w += wa * u0.w;
        acc.x += wb * u1.x; acc.y += wb * u1.y; acc.z += wb * u1.z; acc.w += wb * u1.w;
        k += 2; n -= 2;
    }
    if (n >= 1) {
        int2 e = g_csr[k];
        float w = __int_as_float(e.y);
        float4 u = ((const float4*)(hin + (size_t)e.x * CH))[lane];
        acc.x += w * u.x; acc.y += w * u.y; acc.z += w * u.z; acc.w += w * u.w;
    }
    ((float4*)(hout + (size_t)i * CH))[lane] = acc;
}

// ---------------- launch 5: z = h @ W^T + bias  (f32x2 packed) --------------
__global__ void zgemm_kernel(const float* __restrict__ A,
                             const float* __restrict__ W,
                             const float* __restrict__ bias,
                             float* __restrict__ C) {
    __shared__ float As[32][64 + 4];    // [k][m]
    __shared__ float Bs[32][128 + 4];   // [k][n]
    int tid = threadIdx.x;
    int m0  = blockIdx.x * 64;
    int tm  = tid >> 4;
    int tn  = tid & 15;

    unsigned long long acc2[4][4];      // [row][n-pair]
#pragma unroll
    for (int i = 0; i < 4; i++)
#pragma unroll
        for (int j = 0; j < 4; j++) acc2[i][j] = 0ull;

    for (int kb = 0; kb < 4; kb++) {
        int k0 = kb * 32;
#pragma unroll
        for (int it = 0; it < 8; it++) {
            int idx = it * 256 + tid;
            int m = idx >> 5, k = idx & 31;
            int row = m0 + m;
            As[k][m] = (row < N_NODES) ? A[(size_t)row * CH + k0 + k] : 0.0f;
        }
#pragma unroll
        for (int it = 0; it < 16; it++) {
            int idx = it * 256 + tid;
            int n = idx >> 5, k = idx & 31;
            Bs[k][n] = W[(size_t)n * CH + k0 + k];
        }
        __syncthreads();
#pragma unroll
        for (int k = 0; k < 32; k++) {
            float4 av  = *(const float4*)&As[k][tm * 4];
            float4 bv0 = *(const float4*)&Bs[k][tn * 8];
            float4 bv1 = *(const float4*)&Bs[k][tn * 8 + 4];
            unsigned long long b[4];
            b[0] = pack2(bv0.x, bv0.y);
            b[1] = pack2(bv0.z, bv0.w);
            b[2] = pack2(bv1.x, bv1.y);
            b[3] = pack2(bv1.z, bv1.w);
            unsigned long long a0 = bcast2(av.x), a1 = bcast2(av.y);
            unsigned long long a2 = bcast2(av.z), a3 = bcast2(av.w);
#pragma unroll
            for (int j = 0; j < 4; j++) {
                fma2(acc2[0][j], a0, b[j]);
                fma2(acc2[1][j], a1, b[j]);
                fma2(acc2[2][j], a2, b[j]);
                fma2(acc2[3][j], a3, b[j]);
            }
        }
        __syncthreads();
    }
#pragma unroll
    for (int i = 0; i < 4; i++) {
        int row = m0 + tm * 4 + i;
        if (row >= N_NODES) break;
#pragma unroll
        for (int j = 0; j < 4; j++) {
            float lo, hi;
            unpack2(lo, hi, acc2[i][j]);
            int col = tn * 8 + j * 2;
            C[(size_t)row * CH + col]     = lo + bias[col];
            C[(size_t)row * CH + col + 1] = hi + bias[col + 1];
        }
    }
}

// ---------------- launch 6: decode (k-pair packed f32x2, no movs) -----------
// smem: s4 [32 c4][80 e-padded] float4 ; w4 [32 c4][64 j] float4
#define EIDX(e) ((e) + ((e) >> 2))
#define S4_STRIDE 80
#define DEC_SMEM ((32 * S4_STRIDE + 32 * 64) * 16)

__global__ void __launch_bounds__(256) decode_kernel(
        const float* __restrict__ z,
        const int* __restrict__ eli,
        const float* __restrict__ w1,
        const float* __restrict__ b1,
        const float* __restrict__ w2,
        const float* __restrict__ b2,
        float* __restrict__ out) {
    extern __shared__ ulonglong2 dsm[];
    ulonglong2* s4 = dsm;                    // [c4][EIDX(e)]
    ulonglong2* w4 = dsm + 32 * S4_STRIDE;   // [c4][j]
    __shared__ float acc_sm[64];

    int tid = threadIdx.x;
    int e0  = blockIdx.x * 64;

    // load w1 as float4: w4[c4][j] = w1[j][4c4..4c4+3]
    const float4* w1v = (const float4*)w1;
#pragma unroll
    for (int it = 0; it < 8; it++) {
        int idx = it * 256 + tid;        // 2048 total
        int j = idx >> 5, c4 = idx & 31;
        float4 wv = w1v[j * 32 + c4];
        ((float4*)w4)[c4 * 64 + j] = wv;
    }

    // build s: 4 threads per edge
    {
        int ee = tid >> 2, q = tid & 3;
        int e  = e0 + ee;
        int a  = eli[e];
        int b  = eli[N_LABEL + e];
        const float4* za4 = (const float4*)(z + (size_t)a * CH);
        const float4* zb4 = (const float4*)(z + (size_t)b * CH);
#pragma unroll
        for (int r = 0; r < 8; r++) {
            int c4 = r * 4 + q;
            float4 x1 = za4[c4];
            float4 x2 = zb4[c4];
            float4 sres = make_float4(x1.x * x2.x, x1.y * x2.y,
                                      x1.z * x2.z, x1.w * x2.w);
            ((float4*)s4)[c4 * S4_STRIDE + EIDX(ee)] = sres;
        }
    }
    if (tid < 64) acc_sm[tid] = b2[0];
    __syncthreads();

    int te = tid & 15;   // edges te*4..+3
    int tj = tid >> 4;   // j     tj*4..+3
    unsigned long long acc2[4][4];   // [edge][j] ; lo=even-c sum, hi=odd-c sum
#pragma unroll
    for (int i = 0; i < 4; i++)
#pragma unroll
        for (int j = 0; j < 4; j++) acc2[i][j] = 0ull;

#pragma unroll 2
    for (int c4 = 0; c4 < 32; c4++) {
        ulonglong2 sv[4], wv[4];
#pragma unroll
        for (int ie = 0; ie < 4; ie++)
            sv[ie] = s4[c4 * S4_STRIDE + EIDX(te * 4 + ie)];
#pragma unroll
        for (int jj = 0; jj < 4; jj++)
            wv[jj] = w4[c4 * 64 + tj * 4 + jj];
#pragma unroll
        for (int ie = 0; ie < 4; ie++)
#pragma unroll
            for (int jj = 0; jj < 4; jj++) {
                fma2(acc2[ie][jj], sv[ie].x, wv[jj].x);
                fma2(acc2[ie][jj], sv[ie].y, wv[jj].y);
            }
    }

    float p[4] = {0.0f, 0.0f, 0.0f, 0.0f};
#pragma unroll
    for (int jj = 0; jj < 4; jj++) {
        int j = tj * 4 + jj;
        float bb = b1[j];
        float ww = w2[j];
#pragma unroll
        for (int ie = 0; ie < 4; ie++) {
            float lo, hi;
            unpack2(lo, hi, acc2[ie][jj]);
            float h = lo + hi + bb;
            if (h > 0.0f) p[ie] += h * ww;
        }
    }
#pragma unroll
    for (int ie = 0; ie < 4; ie++)
        atomicAdd(&acc_sm[te * 4 + ie], p[ie]);
    __syncthreads();

    if (tid < 64) out[e0 + tid] = acc_sm[tid];
}

// ---------------- launch 7: cleanup (restore zero-state for replay) ---------
__global__ void cleanup_kernel() {
    int i = blockIdx.x * blockDim.x + threadIdx.x;
    if (i < N_NODES) { g_indeg[i] = 0; g_cursor[i] = 0; }
    if (i < SCAN_BLOCKS) g_scan_state[i] = 0;
}

// ---------------- launch ------------------------------------------------------
extern "C" void kernel_launch(void* const* d_in, const int* in_sizes, int n_in,
                              void* d_out, int out_size) {
    const float* x    = (const float*)d_in[0];
    const int*   ei   = (const int*)  d_in[1];
    const int*   eli  = (const int*)  d_in[2];
    const float* cw   = (const float*)d_in[3];
    const float* cb   = (const float*)d_in[4];
    const float* w1   = (const float*)d_in[5];
    const float* b1   = (const float*)d_in[6];
    const float* w2   = (const float*)d_in[7];
    const float* b2   = (const float*)d_in[8];
    float*       out  = (float*)d_out;

    float *hA, *hB, *zz;
    cudaGetSymbolAddress((void**)&hA, g_hA);
    cudaGetSymbolAddress((void**)&hB, g_hB);
    cudaGetSymbolAddress((void**)&zz, g_z);

    // 0: in-degree (g_indeg zero by static init / cleanup)
    indeg_kernel   <<<(N_EDGES + 255) / 256, 256>>>(ei);
    // 1: fused scan + dinv
    scanF_kernel   <<<SCAN_BLOCKS, SCAN_TPB>>>();
    // 2: CSR fill
    csr_fill_kernel<<<(N_EDGES + 255) / 256, 256>>>(ei);
    // 3,4: 2-hop propagation  (launch index 3 = profiled slot)
    gather_kernel<<<(N_NODES * 32 + 255) / 256, 256>>>(x,  hA);
    gather_kernel<<<(N_NODES * 32 + 255) / 256, 256>>>(hA, hB);
    // 5: z = hB @ W^T + b
    zgemm_kernel<<<(N_NODES + 63) / 64, 256>>>(hB, cw, cb, zz);
    // 6: decode
    cudaFuncSetAttribute(decode_kernel,
                         cudaFuncAttributeMaxDynamicSharedMemorySize, DEC_SMEM);
    decode_kernel<<<N_LABEL / 64, 256, DEC_SMEM>>>(
        zz, eli, w1, b1, w2, b2, out);
    // 7: restore scratch to zero for next replay
    cleanup_kernel<<<(N_NODES + 255) / 256, 256>>>();
}